// round 14
// baseline (speedup 1.0000x reference)
#include <cuda_runtime.h>
#include <cuda_bf16.h>
#include <cuda_fp16.h>
#include <mma.h>
#include <cstdint>
#include <cstddef>

using namespace nvcuda;

#define N_NODES 50000
#define N_ROWS_PAD 50048              // 391 blocks * 128 rows
#define NH1      25088               // 196 blocks * 128 rows (half-split point)
#define N_EDGES 800000
#define SCAN_B  256
#define SCAN_NB ((N_NODES + SCAN_B - 1) / SCAN_B)

// Scratch (allocation-free rule: __device__ globals)
__device__ __half g_S16a[(size_t)N_ROWS_PAD * 128]; // support, layers 1 & 3
__device__ __half g_S16b[(size_t)N_ROWS_PAD * 128]; // support, layers 2 & 4
__device__ float  g_A[(size_t)N_ROWS_PAD * 128];    // aggregation output / next input
__device__ int    g_off[N_NODES + 1];
__device__ int    g_cur[N_NODES];
__device__ int    g_part[SCAN_NB];
__device__ int    g_src_s[N_EDGES];
__device__ float  g_val_s[N_EDGES];
// Split-bf16 weights, row-major [DIN][DOUT]
__device__ __nv_bfloat16 g_whi1[16384], g_wlo1[16384];
__device__ __nv_bfloat16 g_whi2[16384], g_wlo2[16384];
__device__ __nv_bfloat16 g_whi3[8192],  g_wlo3[8192];
__device__ __nv_bfloat16 g_whi4[2048],  g_wlo4[2048];

// ---------------------------------------------------------------------------
// W prep: fp32 W[DIN,DOUT] -> hi/lo bf16 (row-major)
// ---------------------------------------------------------------------------
template <int DIN, int DOUT>
__global__ void prep_w_kernel(const float* __restrict__ W,
                              __nv_bfloat16* __restrict__ whi,
                              __nv_bfloat16* __restrict__ wlo) {
    int idx = blockIdx.x * 256 + threadIdx.x;
    if (idx >= DIN * DOUT) return;
    float w = W[idx];
    __nv_bfloat16 hi = __float2bfloat16(w);
    whi[idx] = hi;
    wlo[idx] = __float2bfloat16(w - __bfloat162float(hi));
}

// ---------------------------------------------------------------------------
// WMMA split-bf16 GEMM:  C16 = act(H) @ W,  D = Ahi*Bhi + Ahi*Blo + Alo*Bhi.
// Full Bhi+Blo resident in smem; A chunk staged once; fp16 output epilogue.
// block0 = row-block offset (for half-grid launches). Stores unguarded
// (C padded to N_ROWS_PAD rows).
// ---------------------------------------------------------------------------
template <int DIN, int DOUT, bool RELU>
__global__ void __launch_bounds__(256) wgemm_kernel(const float* __restrict__ H,
                                                    const __nv_bfloat16* __restrict__ whi,
                                                    const __nv_bfloat16* __restrict__ wlo,
                                                    __half* __restrict__ C16,
                                                    int N, int block0) {
    constexpr int BM   = 128;
    constexpr int KB   = 32;
    constexpr int MW   = (DOUT == 128) ? 2 : (DOUT == 64 ? 4 : 8);
    constexpr int NW   = 8 / MW;
    constexpr int WM   = BM / MW;
    constexpr int WN   = DOUT / NW;
    constexpr int MT   = WM / 16;
    constexpr int NT   = WN / 16;
    constexpr int ASTR = KB + 8;           // 40
    constexpr int BSTR = DOUT + 8;         // 136 / 72 / 40

    extern __shared__ char smem[];
    __nv_bfloat16* Ahi = (__nv_bfloat16*)smem;
    __nv_bfloat16* Alo = Ahi + BM * ASTR;
    __nv_bfloat16* Bhi = Alo + BM * ASTR;
    __nv_bfloat16* Blo = Bhi + DIN * BSTR;

    const int tid    = threadIdx.x;
    const int wid    = tid / 32;
    const int lane   = tid % 32;
    const int warp_m = wid % MW;
    const int warp_n = wid / MW;
    const int row0   = (blockIdx.x + block0) * BM;

    wmma::fragment<wmma::accumulator, 16, 16, 16, float> acc[MT][NT];
#pragma unroll
    for (int i = 0; i < MT; i++)
#pragma unroll
        for (int j = 0; j < NT; j++) wmma::fill_fragment(acc[i][j], 0.0f);

    // Stage full B (hi + lo) once
#pragma unroll
    for (int t = tid; t < DIN * DOUT / 8; t += 256) {
        int kk = t / (DOUT / 8);
        int c8 = t % (DOUT / 8);
        *(uint4*)(Bhi + kk * BSTR + c8 * 8) = *(const uint4*)(whi + kk * DOUT + c8 * 8);
        *(uint4*)(Blo + kk * BSTR + c8 * 8) = *(const uint4*)(wlo + kk * DOUT + c8 * 8);
    }

    for (int k0 = 0; k0 < DIN; k0 += KB) {
        // Stage A chunk: hi and lo in one pass over H
#pragma unroll
        for (int t = tid; t < BM * KB / 4; t += 256) {
            int r = t >> 3;                // KB/4 = 8 float4 per row
            int q = t & 7;
            int row = row0 + r;
            float4 v = make_float4(0.f, 0.f, 0.f, 0.f);
            if (row < N) v = *(const float4*)(H + (size_t)row * DIN + k0 + q * 4);
            if (RELU) {
                v.x = fmaxf(v.x, 0.f); v.y = fmaxf(v.y, 0.f);
                v.z = fmaxf(v.z, 0.f); v.w = fmaxf(v.w, 0.f);
            }
            __nv_bfloat162 h01 = __floats2bfloat162_rn(v.x, v.y);
            __nv_bfloat162 h23 = __floats2bfloat162_rn(v.z, v.w);
            __nv_bfloat162 l01 = __floats2bfloat162_rn(v.x - __bfloat162float(h01.x),
                                                       v.y - __bfloat162float(h01.y));
            __nv_bfloat162 l23 = __floats2bfloat162_rn(v.z - __bfloat162float(h23.x),
                                                       v.w - __bfloat162float(h23.y));
            __nv_bfloat162* ah = (__nv_bfloat162*)(Ahi + r * ASTR + q * 4);
            __nv_bfloat162* al = (__nv_bfloat162*)(Alo + r * ASTR + q * 4);
            ah[0] = h01; ah[1] = h23;
            al[0] = l01; al[1] = l23;
        }
        __syncthreads();   // first iter also covers B staging

#pragma unroll
        for (int kt = 0; kt < KB / 16; kt++) {
            wmma::fragment<wmma::matrix_a, 16, 16, 16, __nv_bfloat16, wmma::row_major> ahi[MT], alo[MT];
            wmma::fragment<wmma::matrix_b, 16, 16, 16, __nv_bfloat16, wmma::row_major> bhi[NT], blo[NT];
#pragma unroll
            for (int i = 0; i < MT; i++) {
                wmma::load_matrix_sync(ahi[i], Ahi + (warp_m * WM + i * 16) * ASTR + kt * 16, ASTR);
                wmma::load_matrix_sync(alo[i], Alo + (warp_m * WM + i * 16) * ASTR + kt * 16, ASTR);
            }
#pragma unroll
            for (int j = 0; j < NT; j++) {
                wmma::load_matrix_sync(bhi[j], Bhi + (k0 + kt * 16) * BSTR + warp_n * WN + j * 16, BSTR);
                wmma::load_matrix_sync(blo[j], Blo + (k0 + kt * 16) * BSTR + warp_n * WN + j * 16, BSTR);
            }
#pragma unroll
            for (int i = 0; i < MT; i++)
#pragma unroll
                for (int j = 0; j < NT; j++) {
                    wmma::mma_sync(acc[i][j], ahi[i], bhi[j], acc[i][j]);
                    wmma::mma_sync(acc[i][j], ahi[i], blo[j], acc[i][j]);
                    wmma::mma_sync(acc[i][j], alo[i], bhi[j], acc[i][j]);
                }
        }
        __syncthreads();
    }

    // fp16 epilogue via per-warp smem scratch (reuses A region; all mma done)
    float* scr = reinterpret_cast<float*>(smem) + wid * 256;
#pragma unroll
    for (int i = 0; i < MT; i++)
#pragma unroll
        for (int j = 0; j < NT; j++) {
            wmma::store_matrix_sync(scr, acc[i][j], 16, wmma::mem_row_major);
            __syncwarp();
            int rr = lane >> 1;
            int cc = (lane & 1) * 8;
            const float* p = scr + rr * 16 + cc;
            __half2 h01 = __floats2half2_rn(p[0], p[1]);
            __half2 h23 = __floats2half2_rn(p[2], p[3]);
            __half2 h45 = __floats2half2_rn(p[4], p[5]);
            __half2 h67 = __floats2half2_rn(p[6], p[7]);
            uint4 u = make_uint4(*(unsigned*)&h01, *(unsigned*)&h23,
                                 *(unsigned*)&h45, *(unsigned*)&h67);
            int row = row0 + warp_m * WM + i * 16 + rr;
            int col = warp_n * WN + j * 16 + cc;
            *reinterpret_cast<uint4*>(C16 + (size_t)row * DOUT + col) = u;
            __syncwarp();
        }
}

// ---------------------------------------------------------------------------
// Counting sort by dst: histogram -> hierarchical exclusive scan -> permute
// ---------------------------------------------------------------------------
__global__ void hist_kernel(const int* __restrict__ dst, int* __restrict__ cnt, int E) {
    int e = blockIdx.x * blockDim.x + threadIdx.x;
    if (e < E) atomicAdd(&cnt[dst[e]], 1);
}

__global__ void __launch_bounds__(SCAN_B) scan_block_kernel(const int* __restrict__ cnt,
                                                            int* __restrict__ off,
                                                            int* __restrict__ part, int n) {
    constexpr int NW = SCAN_B / 32;
    __shared__ int wsum[NW];
    int tid = threadIdx.x;
    int i = blockIdx.x * SCAN_B + tid;
    int v = (i < n) ? cnt[i] : 0;
    int x = v;
#pragma unroll
    for (int o = 1; o < 32; o <<= 1) {
        int y = __shfl_up_sync(0xffffffffu, x, o);
        if ((tid & 31) >= o) x += y;
    }
    if ((tid & 31) == 31) wsum[tid >> 5] = x;
    __syncthreads();
    if (tid < 32) {
        int w = (tid < NW) ? wsum[tid] : 0;
#pragma unroll
        for (int o = 1; o < 32; o <<= 1) {
            int y = __shfl_up_sync(0xffffffffu, w, o);
            if (tid >= o) w += y;
        }
        if (tid < NW) wsum[tid] = w;
    }
    __syncthreads();
    int excl = x - v + ((tid >= 32) ? wsum[(tid >> 5) - 1] : 0);
    if (i < n) off[i] = excl;
    if (tid == SCAN_B - 1) part[blockIdx.x] = excl + v;
}

__global__ void __launch_bounds__(SCAN_B) scan_part_kernel(int* __restrict__ part, int m) {
    constexpr int NW = SCAN_B / 32;
    __shared__ int wsum[NW];
    int tid = threadIdx.x;
    int v = (tid < m) ? part[tid] : 0;
    int x = v;
#pragma unroll
    for (int o = 1; o < 32; o <<= 1) {
        int y = __shfl_up_sync(0xffffffffu, x, o);
        if ((tid & 31) >= o) x += y;
    }
    if ((tid & 31) == 31) wsum[tid >> 5] = x;
    __syncthreads();
    if (tid < 32) {
        int w = (tid < NW) ? wsum[tid] : 0;
#pragma unroll
        for (int o = 1; o < 32; o <<= 1) {
            int y = __shfl_up_sync(0xffffffffu, w, o);
            if (tid >= o) w += y;
        }
        if (tid < NW) wsum[tid] = w;
    }
    __syncthreads();
    int excl = x - v + ((tid >= 32) ? wsum[(tid >> 5) - 1] : 0);
    if (tid < m) part[tid] = excl;
}

__global__ void finalize_scan_kernel(int* __restrict__ off, const int* __restrict__ part,
                                     int* __restrict__ cur, int n, int total) {
    int i = blockIdx.x * blockDim.x + threadIdx.x;
    if (i < n) {
        int o = off[i] + part[blockIdx.x];
        off[i] = o;
        cur[i] = o;
    }
    if (i == 0) off[n] = total;
}

__global__ void permute_kernel(const int* __restrict__ src, const int* __restrict__ dst,
                               const float* __restrict__ val, int* __restrict__ cur,
                               int* __restrict__ src_s, float* __restrict__ val_s, int E) {
    int e = blockIdx.x * blockDim.x + threadIdx.x;
    if (e >= E) return;
    int d = dst[e];
    int pos = atomicAdd(&cur[d], 1);
    src_s[pos] = src[e];
    val_s[pos] = val[e];
}

// ---------------------------------------------------------------------------
// fp16-gather aggregation over node range [node0, node1):
//   out(fp32) = bias + sum_j S16[src]*val  (fp32 accumulate)
// D/8 lanes per node, 16B (8 halves) per lane per edge.
// ---------------------------------------------------------------------------
template <int D>
__global__ void __launch_bounds__(256) agg16_kernel(const __half* __restrict__ S,
                                                    const int* __restrict__ off,
                                                    const int* __restrict__ src_s,
                                                    const float* __restrict__ val_s,
                                                    const float* __restrict__ bias,
                                                    float* __restrict__ out,
                                                    int node0, int node1) {
    constexpr int L = D / 8;
    int t = blockIdx.x * blockDim.x + threadIdx.x;
    int node = node0 + t / L;
    int lane = t % L;
    if (node >= node1) return;

    int beg = __ldg(off + node);
    int end = __ldg(off + node + 1);
    float4 a0 = ((const float4*)bias)[lane * 2];
    float4 a1 = ((const float4*)bias)[lane * 2 + 1];

    int j = beg;
    for (; j + 2 <= end; j += 2) {
        int   s0 = __ldg(src_s + j);
        int   s1 = __ldg(src_s + j + 1);
        float v0 = __ldg(val_s + j);
        float v1 = __ldg(val_s + j + 1);
        uint4 m0 = *(const uint4*)(S + (size_t)s0 * D + lane * 8);
        uint4 m1 = *(const uint4*)(S + (size_t)s1 * D + lane * 8);
        const __half2* h0 = (const __half2*)&m0;
        const __half2* h1 = (const __half2*)&m1;
        float2 f;
        f = __half22float2(h0[0]); a0.x += v0 * f.x; a0.y += v0 * f.y;
        f = __half22float2(h0[1]); a0.z += v0 * f.x; a0.w += v0 * f.y;
        f = __half22float2(h0[2]); a1.x += v0 * f.x; a1.y += v0 * f.y;
        f = __half22float2(h0[3]); a1.z += v0 * f.x; a1.w += v0 * f.y;
        f = __half22float2(h1[0]); a0.x += v1 * f.x; a0.y += v1 * f.y;
        f = __half22float2(h1[1]); a0.z += v1 * f.x; a0.w += v1 * f.y;
        f = __half22float2(h1[2]); a1.x += v1 * f.x; a1.y += v1 * f.y;
        f = __half22float2(h1[3]); a1.z += v1 * f.x; a1.w += v1 * f.y;
    }
    if (j < end) {
        int   s0 = __ldg(src_s + j);
        float v0 = __ldg(val_s + j);
        uint4 m0 = *(const uint4*)(S + (size_t)s0 * D + lane * 8);
        const __half2* h0 = (const __half2*)&m0;
        float2 f;
        f = __half22float2(h0[0]); a0.x += v0 * f.x; a0.y += v0 * f.y;
        f = __half22float2(h0[1]); a0.z += v0 * f.x; a0.w += v0 * f.y;
        f = __half22float2(h0[2]); a1.x += v0 * f.x; a1.y += v0 * f.y;
        f = __half22float2(h0[3]); a1.z += v0 * f.x; a1.w += v0 * f.y;
    }

    float* dst = out + (size_t)node * D + lane * 8;
    *(float4*)dst = a0;
    *(float4*)(dst + 4) = a1;
}

// ---------------------------------------------------------------------------
// Launch: CSR+Wprep on side stream; cross-layer half-split pipelining with
// double-buffered fp16 support (S16a odd layers, S16b even layers).
// ---------------------------------------------------------------------------
extern "C" void kernel_launch(void* const* d_in, const int* in_sizes, int n_in,
                              void* d_out, int out_size) {
    const float* x    = (const float*)d_in[0];
    const int*   esrc = (const int*)d_in[1];
    const int*   edst = (const int*)d_in[2];
    const float* eval = (const float*)d_in[3];
    const float* W1 = (const float*)d_in[4];
    const float* b1 = (const float*)d_in[5];
    const float* W2 = (const float*)d_in[6];
    const float* b2 = (const float*)d_in[7];
    const float* W3 = (const float*)d_in[8];
    const float* b3 = (const float*)d_in[9];
    const float* W4 = (const float*)d_in[10];
    const float* b4 = (const float*)d_in[11];
    float* out = (float*)d_out;

    float* A = nullptr;
    __half *Sa = nullptr, *Sb = nullptr;
    int *off = nullptr, *cur = nullptr, *part = nullptr, *src_s = nullptr;
    float *val_s = nullptr;
    __nv_bfloat16 *wh1, *wl1, *wh2, *wl2, *wh3, *wl3, *wh4, *wl4;
    cudaGetSymbolAddress((void**)&Sa, g_S16a);
    cudaGetSymbolAddress((void**)&Sb, g_S16b);
    cudaGetSymbolAddress((void**)&A, g_A);
    cudaGetSymbolAddress((void**)&off, g_off);
    cudaGetSymbolAddress((void**)&cur, g_cur);
    cudaGetSymbolAddress((void**)&part, g_part);
    cudaGetSymbolAddress((void**)&src_s, g_src_s);
    cudaGetSymbolAddress((void**)&val_s, g_val_s);
    cudaGetSymbolAddress((void**)&wh1, g_whi1);
    cudaGetSymbolAddress((void**)&wl1, g_wlo1);
    cudaGetSymbolAddress((void**)&wh2, g_whi2);
    cudaGetSymbolAddress((void**)&wl2, g_wlo2);
    cudaGetSymbolAddress((void**)&wh3, g_whi3);
    cudaGetSymbolAddress((void**)&wl3, g_wlo3);
    cudaGetSymbolAddress((void**)&wh4, g_whi4);
    cudaGetSymbolAddress((void**)&wl4, g_wlo4);

    const int SM128 = (2 * 128 * 40 + 2 * 128 * 136) * 2;  // 90112
    const int SM64  = (2 * 128 * 40 + 2 * 128 * 72) * 2;   // 57344
    const int SM32  = (2 * 128 * 40 + 2 * 64 * 40) * 2;    // 30720
    cudaFuncSetAttribute(wgemm_kernel<128, 128, false>,
                         cudaFuncAttributeMaxDynamicSharedMemorySize, SM128);
    cudaFuncSetAttribute(wgemm_kernel<128, 128, true>,
                         cudaFuncAttributeMaxDynamicSharedMemorySize, SM128);
    cudaFuncSetAttribute(wgemm_kernel<128, 64, true>,
                         cudaFuncAttributeMaxDynamicSharedMemorySize, SM64);

    static cudaStream_t s_side = nullptr;
    static cudaEvent_t ev_fork, ev_csr, evG[4], evA[4];
    if (s_side == nullptr) {
        cudaStreamCreateWithFlags(&s_side, cudaStreamNonBlocking);
        cudaEventCreateWithFlags(&ev_fork, cudaEventDisableTiming);
        cudaEventCreateWithFlags(&ev_csr, cudaEventDisableTiming);
        for (int i = 0; i < 4; i++) {
            cudaEventCreateWithFlags(&evG[i], cudaEventDisableTiming);
            cudaEventCreateWithFlags(&evA[i], cudaEventDisableTiming);
        }
    }

    const int N = N_NODES;
    const int E = N_EDGES;
    const int GB  = (N + 127) / 128;   // 391 row blocks
    const int GB1 = 196;               // blocks in half 1 (rows [0, NH1))
    const int GB2 = GB - GB1;          // 195

    auto agg_grid = [](int nodes, int L) { return (nodes * L + 255) / 256; };

    // ---- Fork: W2-4 prep + CSR build on side stream ----
    cudaEventRecord(ev_fork, 0);
    cudaStreamWaitEvent(s_side, ev_fork, 0);
    prep_w_kernel<128, 128><<<64, 256, 0, s_side>>>(W2, wh2, wl2);
    prep_w_kernel<128, 64><<<32, 256, 0, s_side>>>(W3, wh3, wl3);
    prep_w_kernel<64, 32><<<8, 256, 0, s_side>>>(W4, wh4, wl4);
    cudaMemsetAsync(cur, 0, N * sizeof(int), s_side);
    hist_kernel<<<(E + 255) / 256, 256, 0, s_side>>>(edst, cur, E);
    scan_block_kernel<<<SCAN_NB, SCAN_B, 0, s_side>>>(cur, off, part, N);
    scan_part_kernel<<<1, SCAN_B, 0, s_side>>>(part, SCAN_NB);
    finalize_scan_kernel<<<SCAN_NB, SCAN_B, 0, s_side>>>(off, part, cur, N, E);
    permute_kernel<<<(E + 255) / 256, 256, 0, s_side>>>(esrc, edst, eval, cur, src_s, val_s, E);
    cudaEventRecord(ev_csr, s_side);

    // ---- Layer 1: gemm full (overlaps side work), then split aggs ----
    prep_w_kernel<128, 128><<<64, 256>>>(W1, wh1, wl1);
    wgemm_kernel<128, 128, false><<<GB, 256, SM128>>>(x, wh1, wl1, Sa, N, 0);
    cudaEventRecord(evG[0], 0);

    cudaStreamWaitEvent(0, ev_csr, 0);
    agg16_kernel<128><<<agg_grid(NH1, 16), 256>>>(Sa, off, src_s, val_s, b1, A, 0, NH1);
    cudaStreamWaitEvent(s_side, evG[0], 0);   // side already has CSR done in-order
    agg16_kernel<128><<<agg_grid(N - NH1, 16), 256, 0, s_side>>>(Sa, off, src_s, val_s, b1, A, NH1, N);
    cudaEventRecord(evA[0], s_side);

    // ---- Layer 2: gemm h1 overlaps agg1 h2 ----
    wgemm_kernel<128, 128, true><<<GB1, 256, SM128>>>(A, wh2, wl2, Sb, N, 0);
    cudaStreamWaitEvent(0, evA[0], 0);
    wgemm_kernel<128, 128, true><<<GB2, 256, SM128>>>(A, wh2, wl2, Sb, N, GB1);
    cudaEventRecord(evG[1], 0);

    agg16_kernel<128><<<agg_grid(NH1, 16), 256>>>(Sb, off, src_s, val_s, b2, A, 0, NH1);
    cudaStreamWaitEvent(s_side, evG[1], 0);
    agg16_kernel<128><<<agg_grid(N - NH1, 16), 256, 0, s_side>>>(Sb, off, src_s, val_s, b2, A, NH1, N);
    cudaEventRecord(evA[1], s_side);

    // ---- Layer 3: gemm h1 overlaps agg2 h2 ----
    wgemm_kernel<128, 64, true><<<GB1, 256, SM64>>>(A, wh3, wl3, Sa, N, 0);
    cudaStreamWaitEvent(0, evA[1], 0);
    wgemm_kernel<128, 64, true><<<GB2, 256, SM64>>>(A, wh3, wl3, Sa, N, GB1);
    cudaEventRecord(evG[2], 0);

    agg16_kernel<64><<<agg_grid(NH1, 8), 256>>>(Sa, off, src_s, val_s, b3, A, 0, NH1);
    cudaStreamWaitEvent(s_side, evG[2], 0);
    agg16_kernel<64><<<agg_grid(N - NH1, 8), 256, 0, s_side>>>(Sa, off, src_s, val_s, b3, A, NH1, N);
    cudaEventRecord(evA[2], s_side);

    // ---- Layer 4: gemm h1 overlaps agg3 h2; agg4 full -> d_out ----
    wgemm_kernel<64, 32, true><<<GB1, 256, SM32>>>(A, wh4, wl4, Sb, N, 0);
    cudaStreamWaitEvent(0, evA[2], 0);
    wgemm_kernel<64, 32, true><<<GB2, 256, SM32>>>(A, wh4, wl4, Sb, N, GB1);

    agg16_kernel<32><<<agg_grid(N, 4), 256>>>(Sb, off, src_s, val_s, b4, out, 0, N);
}

// round 16
// speedup vs baseline: 1.1557x; 1.1557x over previous
#include <cuda_runtime.h>
#include <cuda_bf16.h>
#include <cuda_fp16.h>
#include <mma.h>
#include <cstdint>
#include <cstddef>

using namespace nvcuda;

#define N_NODES 50000
#define N_ROWS_PAD 50048              // 391 blocks * 128 rows
#define N_EDGES 800000
#define SCAN_B  256
#define SCAN_NB ((N_NODES + SCAN_B - 1) / SCAN_B)

// Scratch (allocation-free rule: __device__ globals)
__device__ __half g_S16[(size_t)N_ROWS_PAD * 128]; // fp16 support (all layers)
__device__ float  g_A[(size_t)N_ROWS_PAD * 128];   // aggregation output / next input
__device__ int    g_off[N_NODES + 1];
__device__ int    g_cur[N_NODES];
__device__ int    g_part[SCAN_NB];
__device__ int    g_src_s[N_EDGES];
__device__ float  g_val_s[N_EDGES];
// Split-bf16 weights, row-major [DIN][DOUT]
__device__ __nv_bfloat16 g_whi1[16384], g_wlo1[16384];
__device__ __nv_bfloat16 g_whi2[16384], g_wlo2[16384];
__device__ __nv_bfloat16 g_whi3[8192],  g_wlo3[8192];
__device__ __nv_bfloat16 g_whi4[2048],  g_wlo4[2048];

// ---------------------------------------------------------------------------
// W prep: fp32 W[DIN,DOUT] -> hi/lo bf16 (row-major)
// ---------------------------------------------------------------------------
template <int DIN, int DOUT>
__global__ void prep_w_kernel(const float* __restrict__ W,
                              __nv_bfloat16* __restrict__ whi,
                              __nv_bfloat16* __restrict__ wlo) {
    int idx = blockIdx.x * 256 + threadIdx.x;
    if (idx >= DIN * DOUT) return;
    float w = W[idx];
    __nv_bfloat16 hi = __float2bfloat16(w);
    whi[idx] = hi;
    wlo[idx] = __float2bfloat16(w - __bfloat162float(hi));
}

// ---------------------------------------------------------------------------
// WMMA split-bf16 GEMM:  C16 = act(H) @ W,  D = Ahi*Bhi + Ahi*Blo + Alo*Bhi.
// Full Bhi+Blo resident in smem; A chunk staged once (hi+lo together);
// fp16 output epilogue via per-warp smem scratch.
// Stores unguarded (C padded to N_ROWS_PAD rows).
// ---------------------------------------------------------------------------
template <int DIN, int DOUT, bool RELU>
__global__ void __launch_bounds__(256) wgemm_kernel(const float* __restrict__ H,
                                                    const __nv_bfloat16* __restrict__ whi,
                                                    const __nv_bfloat16* __restrict__ wlo,
                                                    __half* __restrict__ C16, int N) {
    constexpr int BM   = 128;
    constexpr int KB   = 32;
    constexpr int MW   = (DOUT == 128) ? 2 : (DOUT == 64 ? 4 : 8);
    constexpr int NW   = 8 / MW;
    constexpr int WM   = BM / MW;
    constexpr int WN   = DOUT / NW;
    constexpr int MT   = WM / 16;
    constexpr int NT   = WN / 16;
    constexpr int ASTR = KB + 8;           // 40
    constexpr int BSTR = DOUT + 8;         // 136 / 72 / 40

    extern __shared__ char smem[];
    __nv_bfloat16* Ahi = (__nv_bfloat16*)smem;
    __nv_bfloat16* Alo = Ahi + BM * ASTR;
    __nv_bfloat16* Bhi = Alo + BM * ASTR;
    __nv_bfloat16* Blo = Bhi + DIN * BSTR;

    const int tid    = threadIdx.x;
    const int wid    = tid / 32;
    const int lane   = tid % 32;
    const int warp_m = wid % MW;
    const int warp_n = wid / MW;
    const int row0   = blockIdx.x * BM;

    wmma::fragment<wmma::accumulator, 16, 16, 16, float> acc[MT][NT];
#pragma unroll
    for (int i = 0; i < MT; i++)
#pragma unroll
        for (int j = 0; j < NT; j++) wmma::fill_fragment(acc[i][j], 0.0f);

    // Stage full B (hi + lo) once
#pragma unroll
    for (int t = tid; t < DIN * DOUT / 8; t += 256) {
        int kk = t / (DOUT / 8);
        int c8 = t % (DOUT / 8);
        *(uint4*)(Bhi + kk * BSTR + c8 * 8) = *(const uint4*)(whi + kk * DOUT + c8 * 8);
        *(uint4*)(Blo + kk * BSTR + c8 * 8) = *(const uint4*)(wlo + kk * DOUT + c8 * 8);
    }

    for (int k0 = 0; k0 < DIN; k0 += KB) {
        // Stage A chunk: hi and lo in one pass over H
#pragma unroll
        for (int t = tid; t < BM * KB / 4; t += 256) {
            int r = t >> 3;                // KB/4 = 8 float4 per row
            int q = t & 7;
            int row = row0 + r;
            float4 v = make_float4(0.f, 0.f, 0.f, 0.f);
            if (row < N) v = *(const float4*)(H + (size_t)row * DIN + k0 + q * 4);
            if (RELU) {
                v.x = fmaxf(v.x, 0.f); v.y = fmaxf(v.y, 0.f);
                v.z = fmaxf(v.z, 0.f); v.w = fmaxf(v.w, 0.f);
            }
            __nv_bfloat162 h01 = __floats2bfloat162_rn(v.x, v.y);
            __nv_bfloat162 h23 = __floats2bfloat162_rn(v.z, v.w);
            __nv_bfloat162 l01 = __floats2bfloat162_rn(v.x - __bfloat162float(h01.x),
                                                       v.y - __bfloat162float(h01.y));
            __nv_bfloat162 l23 = __floats2bfloat162_rn(v.z - __bfloat162float(h23.x),
                                                       v.w - __bfloat162float(h23.y));
            __nv_bfloat162* ah = (__nv_bfloat162*)(Ahi + r * ASTR + q * 4);
            __nv_bfloat162* al = (__nv_bfloat162*)(Alo + r * ASTR + q * 4);
            ah[0] = h01; ah[1] = h23;
            al[0] = l01; al[1] = l23;
        }
        __syncthreads();   // first iter also covers B staging

#pragma unroll
        for (int kt = 0; kt < KB / 16; kt++) {
            wmma::fragment<wmma::matrix_a, 16, 16, 16, __nv_bfloat16, wmma::row_major> ahi[MT], alo[MT];
            wmma::fragment<wmma::matrix_b, 16, 16, 16, __nv_bfloat16, wmma::row_major> bhi[NT], blo[NT];
#pragma unroll
            for (int i = 0; i < MT; i++) {
                wmma::load_matrix_sync(ahi[i], Ahi + (warp_m * WM + i * 16) * ASTR + kt * 16, ASTR);
                wmma::load_matrix_sync(alo[i], Alo + (warp_m * WM + i * 16) * ASTR + kt * 16, ASTR);
            }
#pragma unroll
            for (int j = 0; j < NT; j++) {
                wmma::load_matrix_sync(bhi[j], Bhi + (k0 + kt * 16) * BSTR + warp_n * WN + j * 16, BSTR);
                wmma::load_matrix_sync(blo[j], Blo + (k0 + kt * 16) * BSTR + warp_n * WN + j * 16, BSTR);
            }
#pragma unroll
            for (int i = 0; i < MT; i++)
#pragma unroll
                for (int j = 0; j < NT; j++) {
                    wmma::mma_sync(acc[i][j], ahi[i], bhi[j], acc[i][j]);
                    wmma::mma_sync(acc[i][j], ahi[i], blo[j], acc[i][j]);
                    wmma::mma_sync(acc[i][j], alo[i], bhi[j], acc[i][j]);
                }
        }
        __syncthreads();
    }

    // fp16 epilogue via per-warp smem scratch (reuses A region; all mma done)
    float* scr = reinterpret_cast<float*>(smem) + wid * 256;
#pragma unroll
    for (int i = 0; i < MT; i++)
#pragma unroll
        for (int j = 0; j < NT; j++) {
            wmma::store_matrix_sync(scr, acc[i][j], 16, wmma::mem_row_major);
            __syncwarp();
            int rr = lane >> 1;
            int cc = (lane & 1) * 8;
            const float* p = scr + rr * 16 + cc;
            __half2 h01 = __floats2half2_rn(p[0], p[1]);
            __half2 h23 = __floats2half2_rn(p[2], p[3]);
            __half2 h45 = __floats2half2_rn(p[4], p[5]);
            __half2 h67 = __floats2half2_rn(p[6], p[7]);
            uint4 u = make_uint4(*(unsigned*)&h01, *(unsigned*)&h23,
                                 *(unsigned*)&h45, *(unsigned*)&h67);
            int row = row0 + warp_m * WM + i * 16 + rr;
            int col = warp_n * WN + j * 16 + cc;
            *reinterpret_cast<uint4*>(C16 + (size_t)row * DOUT + col) = u;
            __syncwarp();
        }
}

// ---------------------------------------------------------------------------
// Counting sort by dst: histogram -> hierarchical exclusive scan -> permute
// ---------------------------------------------------------------------------
__global__ void hist_kernel(const int* __restrict__ dst, int* __restrict__ cnt, int E) {
    int e = blockIdx.x * blockDim.x + threadIdx.x;
    if (e < E) atomicAdd(&cnt[dst[e]], 1);
}

__global__ void __launch_bounds__(SCAN_B) scan_block_kernel(const int* __restrict__ cnt,
                                                            int* __restrict__ off,
                                                            int* __restrict__ part, int n) {
    constexpr int NW = SCAN_B / 32;
    __shared__ int wsum[NW];
    int tid = threadIdx.x;
    int i = blockIdx.x * SCAN_B + tid;
    int v = (i < n) ? cnt[i] : 0;
    int x = v;
#pragma unroll
    for (int o = 1; o < 32; o <<= 1) {
        int y = __shfl_up_sync(0xffffffffu, x, o);
        if ((tid & 31) >= o) x += y;
    }
    if ((tid & 31) == 31) wsum[tid >> 5] = x;
    __syncthreads();
    if (tid < 32) {
        int w = (tid < NW) ? wsum[tid] : 0;
#pragma unroll
        for (int o = 1; o < 32; o <<= 1) {
            int y = __shfl_up_sync(0xffffffffu, w, o);
            if (tid >= o) w += y;
        }
        if (tid < NW) wsum[tid] = w;
    }
    __syncthreads();
    int excl = x - v + ((tid >= 32) ? wsum[(tid >> 5) - 1] : 0);
    if (i < n) off[i] = excl;
    if (tid == SCAN_B - 1) part[blockIdx.x] = excl + v;
}

__global__ void __launch_bounds__(SCAN_B) scan_part_kernel(int* __restrict__ part, int m) {
    constexpr int NW = SCAN_B / 32;
    __shared__ int wsum[NW];
    int tid = threadIdx.x;
    int v = (tid < m) ? part[tid] : 0;
    int x = v;
#pragma unroll
    for (int o = 1; o < 32; o <<= 1) {
        int y = __shfl_up_sync(0xffffffffu, x, o);
        if ((tid & 31) >= o) x += y;
    }
    if ((tid & 31) == 31) wsum[tid >> 5] = x;
    __syncthreads();
    if (tid < 32) {
        int w = (tid < NW) ? wsum[tid] : 0;
#pragma unroll
        for (int o = 1; o < 32; o <<= 1) {
            int y = __shfl_up_sync(0xffffffffu, w, o);
            if (tid >= o) w += y;
        }
        if (tid < NW) wsum[tid] = w;
    }
    __syncthreads();
    int excl = x - v + ((tid >= 32) ? wsum[(tid >> 5) - 1] : 0);
    if (tid < m) part[tid] = excl;
}

__global__ void finalize_scan_kernel(int* __restrict__ off, const int* __restrict__ part,
                                     int* __restrict__ cur, int n, int total) {
    int i = blockIdx.x * blockDim.x + threadIdx.x;
    if (i < n) {
        int o = off[i] + part[blockIdx.x];
        off[i] = o;
        cur[i] = o;
    }
    if (i == 0) off[n] = total;
}

__global__ void permute_kernel(const int* __restrict__ src, const int* __restrict__ dst,
                               const float* __restrict__ val, int* __restrict__ cur,
                               int* __restrict__ src_s, float* __restrict__ val_s, int E) {
    int e = blockIdx.x * blockDim.x + threadIdx.x;
    if (e >= E) return;
    int d = dst[e];
    int pos = atomicAdd(&cur[d], 1);
    src_s[pos] = src[e];
    val_s[pos] = val[e];
}

// ---------------------------------------------------------------------------
// fp16-gather aggregation: out(fp32) = bias + sum_j S16[src]*val (fp32 accum)
// D/8 lanes per node, 16B (8 halves) per lane per edge.
// ---------------------------------------------------------------------------
template <int D>
__global__ void __launch_bounds__(256) agg16_kernel(const __half* __restrict__ S,
                                                    const int* __restrict__ off,
                                                    const int* __restrict__ src_s,
                                                    const float* __restrict__ val_s,
                                                    const float* __restrict__ bias,
                                                    float* __restrict__ out, int N) {
    constexpr int L = D / 8;
    int t = blockIdx.x * blockDim.x + threadIdx.x;
    int node = t / L;
    int lane = t % L;
    if (node >= N) return;

    int beg = __ldg(off + node);
    int end = __ldg(off + node + 1);
    float4 a0 = ((const float4*)bias)[lane * 2];
    float4 a1 = ((const float4*)bias)[lane * 2 + 1];

    int j = beg;
    for (; j + 2 <= end; j += 2) {
        int   s0 = __ldg(src_s + j);
        int   s1 = __ldg(src_s + j + 1);
        float v0 = __ldg(val_s + j);
        float v1 = __ldg(val_s + j + 1);
        uint4 m0 = *(const uint4*)(S + (size_t)s0 * D + lane * 8);
        uint4 m1 = *(const uint4*)(S + (size_t)s1 * D + lane * 8);
        const __half2* h0 = (const __half2*)&m0;
        const __half2* h1 = (const __half2*)&m1;
        float2 f;
        f = __half22float2(h0[0]); a0.x += v0 * f.x; a0.y += v0 * f.y;
        f = __half22float2(h0[1]); a0.z += v0 * f.x; a0.w += v0 * f.y;
        f = __half22float2(h0[2]); a1.x += v0 * f.x; a1.y += v0 * f.y;
        f = __half22float2(h0[3]); a1.z += v0 * f.x; a1.w += v0 * f.y;
        f = __half22float2(h1[0]); a0.x += v1 * f.x; a0.y += v1 * f.y;
        f = __half22float2(h1[1]); a0.z += v1 * f.x; a0.w += v1 * f.y;
        f = __half22float2(h1[2]); a1.x += v1 * f.x; a1.y += v1 * f.y;
        f = __half22float2(h1[3]); a1.z += v1 * f.x; a1.w += v1 * f.y;
    }
    if (j < end) {
        int   s0 = __ldg(src_s + j);
        float v0 = __ldg(val_s + j);
        uint4 m0 = *(const uint4*)(S + (size_t)s0 * D + lane * 8);
        const __half2* h0 = (const __half2*)&m0;
        float2 f;
        f = __half22float2(h0[0]); a0.x += v0 * f.x; a0.y += v0 * f.y;
        f = __half22float2(h0[1]); a0.z += v0 * f.x; a0.w += v0 * f.y;
        f = __half22float2(h0[2]); a1.x += v0 * f.x; a1.y += v0 * f.y;
        f = __half22float2(h0[3]); a1.z += v0 * f.x; a1.w += v0 * f.y;
    }

    float* dst = out + (size_t)node * D + lane * 8;
    *(float4*)dst = a0;
    *(float4*)(dst + 4) = a1;
}

// ---------------------------------------------------------------------------
// Launch (round-12 proven topology; all layers fp16 support path)
// ---------------------------------------------------------------------------
extern "C" void kernel_launch(void* const* d_in, const int* in_sizes, int n_in,
                              void* d_out, int out_size) {
    const float* x    = (const float*)d_in[0];
    const int*   esrc = (const int*)d_in[1];
    const int*   edst = (const int*)d_in[2];
    const float* eval = (const float*)d_in[3];
    const float* W1 = (const float*)d_in[4];
    const float* b1 = (const float*)d_in[5];
    const float* W2 = (const float*)d_in[6];
    const float* b2 = (const float*)d_in[7];
    const float* W3 = (const float*)d_in[8];
    const float* b3 = (const float*)d_in[9];
    const float* W4 = (const float*)d_in[10];
    const float* b4 = (const float*)d_in[11];
    float* out = (float*)d_out;

    float* A = nullptr;
    __half* S16 = nullptr;
    int *off = nullptr, *cur = nullptr, *part = nullptr, *src_s = nullptr;
    float *val_s = nullptr;
    __nv_bfloat16 *wh1, *wl1, *wh2, *wl2, *wh3, *wl3, *wh4, *wl4;
    cudaGetSymbolAddress((void**)&S16, g_S16);
    cudaGetSymbolAddress((void**)&A, g_A);
    cudaGetSymbolAddress((void**)&off, g_off);
    cudaGetSymbolAddress((void**)&cur, g_cur);
    cudaGetSymbolAddress((void**)&part, g_part);
    cudaGetSymbolAddress((void**)&src_s, g_src_s);
    cudaGetSymbolAddress((void**)&val_s, g_val_s);
    cudaGetSymbolAddress((void**)&wh1, g_whi1);
    cudaGetSymbolAddress((void**)&wl1, g_wlo1);
    cudaGetSymbolAddress((void**)&wh2, g_whi2);
    cudaGetSymbolAddress((void**)&wl2, g_wlo2);
    cudaGetSymbolAddress((void**)&wh3, g_whi3);
    cudaGetSymbolAddress((void**)&wl3, g_wlo3);
    cudaGetSymbolAddress((void**)&wh4, g_whi4);
    cudaGetSymbolAddress((void**)&wl4, g_wlo4);

    // smem sizes: (2*BM*ASTR + 2*DIN*BSTR) * 2 bytes
    const int SM128 = (2 * 128 * 40 + 2 * 128 * 136) * 2;  // 90112
    const int SM64  = (2 * 128 * 40 + 2 * 128 * 72) * 2;   // 57344
    const int SM32  = (2 * 128 * 40 + 2 * 64 * 40) * 2;    // 30720
    cudaFuncSetAttribute(wgemm_kernel<128, 128, false>,
                         cudaFuncAttributeMaxDynamicSharedMemorySize, SM128);
    cudaFuncSetAttribute(wgemm_kernel<128, 128, true>,
                         cudaFuncAttributeMaxDynamicSharedMemorySize, SM128);
    cudaFuncSetAttribute(wgemm_kernel<128, 64, true>,
                         cudaFuncAttributeMaxDynamicSharedMemorySize, SM64);

    // Persistent side stream + events
    static cudaStream_t s_side = nullptr;
    static cudaEvent_t  ev_fork = nullptr, ev_join = nullptr;
    if (s_side == nullptr) {
        cudaStreamCreateWithFlags(&s_side, cudaStreamNonBlocking);
        cudaEventCreateWithFlags(&ev_fork, cudaEventDisableTiming);
        cudaEventCreateWithFlags(&ev_join, cudaEventDisableTiming);
    }

    const int N = N_NODES;
    const int E = N_EDGES;
    const int tile_grid = (N + 127) / 128;

    // ---- Fork: W2-4 prep + CSR build on side stream ----
    cudaEventRecord(ev_fork, 0);
    cudaStreamWaitEvent(s_side, ev_fork, 0);

    prep_w_kernel<128, 128><<<64, 256, 0, s_side>>>(W2, wh2, wl2);
    prep_w_kernel<128, 64><<<32, 256, 0, s_side>>>(W3, wh3, wl3);
    prep_w_kernel<64, 32><<<8, 256, 0, s_side>>>(W4, wh4, wl4);
    cudaMemsetAsync(cur, 0, N * sizeof(int), s_side);
    hist_kernel<<<(E + 255) / 256, 256, 0, s_side>>>(edst, cur, E);
    scan_block_kernel<<<SCAN_NB, SCAN_B, 0, s_side>>>(cur, off, part, N);
    scan_part_kernel<<<1, SCAN_B, 0, s_side>>>(part, SCAN_NB);
    finalize_scan_kernel<<<SCAN_NB, SCAN_B, 0, s_side>>>(off, part, cur, N, E);
    permute_kernel<<<(E + 255) / 256, 256, 0, s_side>>>(esrc, edst, eval, cur, src_s, val_s, E);
    cudaEventRecord(ev_join, s_side);

    // ---- Layer 1 ----
    prep_w_kernel<128, 128><<<64, 256>>>(W1, wh1, wl1);
    wgemm_kernel<128, 128, false><<<tile_grid, 256, SM128>>>(x, wh1, wl1, S16, N);

    cudaStreamWaitEvent(0, ev_join, 0);
    agg16_kernel<128><<<(N * 16 + 255) / 256, 256>>>(S16, off, src_s, val_s, b1, A, N);

    // ---- Layer 2 ----
    wgemm_kernel<128, 128, true><<<tile_grid, 256, SM128>>>(A, wh2, wl2, S16, N);
    agg16_kernel<128><<<(N * 16 + 255) / 256, 256>>>(S16, off, src_s, val_s, b2, A, N);

    // ---- Layer 3 ----
    wgemm_kernel<128, 64, true><<<tile_grid, 256, SM64>>>(A, wh3, wl3, S16, N);
    agg16_kernel<64><<<(N * 8 + 255) / 256, 256>>>(S16, off, src_s, val_s, b3, A, N);

    // ---- Layer 4 (fp16 path) -> d_out ----
    wgemm_kernel<64, 32, true><<<tile_grid, 256, SM32>>>(A, wh4, wl4, S16, N);
    agg16_kernel<32><<<(N * 4 + 255) / 256, 256>>>(S16, off, src_s, val_s, b4, out, N);
}

// round 17
// speedup vs baseline: 1.4320x; 1.2391x over previous
#include <cuda_runtime.h>
#include <cuda_bf16.h>
#include <cuda_fp16.h>
#include <mma.h>
#include <cstdint>
#include <cstddef>

using namespace nvcuda;

#define N_NODES 50000
#define N_ROWS_PAD 50048              // 391 blocks * 128 rows
#define N_EDGES 800000
#define SCAN_B  256
#define SCAN_NB ((N_NODES + SCAN_B - 1) / SCAN_B)

// Scratch (allocation-free rule: __device__ globals)
__device__ __half g_S16[(size_t)N_ROWS_PAD * 128]; // fp16 support (all layers)
__device__ float  g_A[(size_t)N_ROWS_PAD * 128];   // aggregation output / next input
__device__ int    g_off[N_NODES + 1];
__device__ int    g_cur[N_NODES];
__device__ int    g_part[SCAN_NB];
__device__ int    g_src_s[N_EDGES];
__device__ float  g_val_s[N_EDGES];
// fp16 weights, row-major [DIN][DOUT]
__device__ __half g_w16_1[16384];
__device__ __half g_w16_2[16384];
__device__ __half g_w16_3[8192];
__device__ __half g_w16_4[2048];

// ---------------------------------------------------------------------------
// W prep: fp32 W[DIN,DOUT] -> fp16 (row-major)
// ---------------------------------------------------------------------------
template <int DIN, int DOUT>
__global__ void prep_w_kernel(const float* __restrict__ W, __half* __restrict__ w16) {
    int idx = blockIdx.x * 256 + threadIdx.x;
    if (idx >= DIN * DOUT) return;
    w16[idx] = __float2half_rn(W[idx]);
}

// ---------------------------------------------------------------------------
// WMMA fp16 GEMM:  C16 = act(H) @ W   (fp16 operands, fp32 accumulate)
// Full B resident in smem; A chunk staged per K-tile; fp16 output epilogue
// via per-warp smem scratch. Stores unguarded (C padded to N_ROWS_PAD rows).
// ---------------------------------------------------------------------------
template <int DIN, int DOUT, bool RELU>
__global__ void __launch_bounds__(256) wgemm_kernel(const float* __restrict__ H,
                                                    const __half* __restrict__ w16,
                                                    __half* __restrict__ C16, int N) {
    constexpr int BM   = 128;
    constexpr int KB   = 32;
    constexpr int MW   = (DOUT == 128) ? 2 : (DOUT == 64 ? 4 : 8);
    constexpr int NW   = 8 / MW;
    constexpr int WM   = BM / MW;
    constexpr int WN   = DOUT / NW;
    constexpr int MT   = WM / 16;
    constexpr int NT   = WN / 16;
    constexpr int ASTR = KB + 8;           // 40 halves = 80 B (16B-aligned rows)
    constexpr int BSTR = DOUT + 8;         // 136 / 72 / 40

    extern __shared__ char smem[];
    __half* As = (__half*)smem;
    __half* Bs = As + BM * ASTR;

    const int tid    = threadIdx.x;
    const int wid    = tid / 32;
    const int lane   = tid % 32;
    const int warp_m = wid % MW;
    const int warp_n = wid / MW;
    const int row0   = blockIdx.x * BM;

    wmma::fragment<wmma::accumulator, 16, 16, 16, float> acc[MT][NT];
#pragma unroll
    for (int i = 0; i < MT; i++)
#pragma unroll
        for (int j = 0; j < NT; j++) wmma::fill_fragment(acc[i][j], 0.0f);

    // Stage full B once
#pragma unroll
    for (int t = tid; t < DIN * DOUT / 8; t += 256) {
        int kk = t / (DOUT / 8);
        int c8 = t % (DOUT / 8);
        *(uint4*)(Bs + kk * BSTR + c8 * 8) = *(const uint4*)(w16 + kk * DOUT + c8 * 8);
    }

    for (int k0 = 0; k0 < DIN; k0 += KB) {
        // Stage A chunk: fp32 -> fp16
#pragma unroll
        for (int t = tid; t < BM * KB / 4; t += 256) {
            int r = t >> 3;                // KB/4 = 8 float4 per row
            int q = t & 7;
            int row = row0 + r;
            float4 v = make_float4(0.f, 0.f, 0.f, 0.f);
            if (row < N) v = *(const float4*)(H + (size_t)row * DIN + k0 + q * 4);
            if (RELU) {
                v.x = fmaxf(v.x, 0.f); v.y = fmaxf(v.y, 0.f);
                v.z = fmaxf(v.z, 0.f); v.w = fmaxf(v.w, 0.f);
            }
            __half2 h01 = __floats2half2_rn(v.x, v.y);
            __half2 h23 = __floats2half2_rn(v.z, v.w);
            __half2* a = (__half2*)(As + r * ASTR + q * 4);
            a[0] = h01; a[1] = h23;
        }
        __syncthreads();   // first iter also covers B staging

#pragma unroll
        for (int kt = 0; kt < KB / 16; kt++) {
            wmma::fragment<wmma::matrix_a, 16, 16, 16, __half, wmma::row_major> a[MT];
            wmma::fragment<wmma::matrix_b, 16, 16, 16, __half, wmma::row_major> b[NT];
#pragma unroll
            for (int i = 0; i < MT; i++)
                wmma::load_matrix_sync(a[i], As + (warp_m * WM + i * 16) * ASTR + kt * 16, ASTR);
#pragma unroll
            for (int j = 0; j < NT; j++)
                wmma::load_matrix_sync(b[j], Bs + (k0 + kt * 16) * BSTR + warp_n * WN + j * 16, BSTR);
#pragma unroll
            for (int i = 0; i < MT; i++)
#pragma unroll
                for (int j = 0; j < NT; j++)
                    wmma::mma_sync(acc[i][j], a[i], b[j], acc[i][j]);
        }
        __syncthreads();
    }

    // fp16 epilogue via per-warp smem scratch (reuses A region; all mma done)
    float* scr = reinterpret_cast<float*>(smem) + wid * 256;
#pragma unroll
    for (int i = 0; i < MT; i++)
#pragma unroll
        for (int j = 0; j < NT; j++) {
            wmma::store_matrix_sync(scr, acc[i][j], 16, wmma::mem_row_major);
            __syncwarp();
            int rr = lane >> 1;
            int cc = (lane & 1) * 8;
            const float* p = scr + rr * 16 + cc;
            __half2 h01 = __floats2half2_rn(p[0], p[1]);
            __half2 h23 = __floats2half2_rn(p[2], p[3]);
            __half2 h45 = __floats2half2_rn(p[4], p[5]);
            __half2 h67 = __floats2half2_rn(p[6], p[7]);
            uint4 u = make_uint4(*(unsigned*)&h01, *(unsigned*)&h23,
                                 *(unsigned*)&h45, *(unsigned*)&h67);
            int row = row0 + warp_m * WM + i * 16 + rr;
            int col = warp_n * WN + j * 16 + cc;
            *reinterpret_cast<uint4*>(C16 + (size_t)row * DOUT + col) = u;
            __syncwarp();
        }
}

// ---------------------------------------------------------------------------
// Counting sort by dst: histogram -> hierarchical exclusive scan -> permute
// ---------------------------------------------------------------------------
__global__ void hist_kernel(const int* __restrict__ dst, int* __restrict__ cnt, int E) {
    int e = blockIdx.x * blockDim.x + threadIdx.x;
    if (e < E) atomicAdd(&cnt[dst[e]], 1);
}

__global__ void __launch_bounds__(SCAN_B) scan_block_kernel(const int* __restrict__ cnt,
                                                            int* __restrict__ off,
                                                            int* __restrict__ part, int n) {
    constexpr int NW = SCAN_B / 32;
    __shared__ int wsum[NW];
    int tid = threadIdx.x;
    int i = blockIdx.x * SCAN_B + tid;
    int v = (i < n) ? cnt[i] : 0;
    int x = v;
#pragma unroll
    for (int o = 1; o < 32; o <<= 1) {
        int y = __shfl_up_sync(0xffffffffu, x, o);
        if ((tid & 31) >= o) x += y;
    }
    if ((tid & 31) == 31) wsum[tid >> 5] = x;
    __syncthreads();
    if (tid < 32) {
        int w = (tid < NW) ? wsum[tid] : 0;
#pragma unroll
        for (int o = 1; o < 32; o <<= 1) {
            int y = __shfl_up_sync(0xffffffffu, w, o);
            if (tid >= o) w += y;
        }
        if (tid < NW) wsum[tid] = w;
    }
    __syncthreads();
    int excl = x - v + ((tid >= 32) ? wsum[(tid >> 5) - 1] : 0);
    if (i < n) off[i] = excl;
    if (tid == SCAN_B - 1) part[blockIdx.x] = excl + v;
}

__global__ void __launch_bounds__(SCAN_B) scan_part_kernel(int* __restrict__ part, int m) {
    constexpr int NW = SCAN_B / 32;
    __shared__ int wsum[NW];
    int tid = threadIdx.x;
    int v = (tid < m) ? part[tid] : 0;
    int x = v;
#pragma unroll
    for (int o = 1; o < 32; o <<= 1) {
        int y = __shfl_up_sync(0xffffffffu, x, o);
        if ((tid & 31) >= o) x += y;
    }
    if ((tid & 31) == 31) wsum[tid >> 5] = x;
    __syncthreads();
    if (tid < 32) {
        int w = (tid < NW) ? wsum[tid] : 0;
#pragma unroll
        for (int o = 1; o < 32; o <<= 1) {
            int y = __shfl_up_sync(0xffffffffu, w, o);
            if (tid >= o) w += y;
        }
        if (tid < NW) wsum[tid] = w;
    }
    __syncthreads();
    int excl = x - v + ((tid >= 32) ? wsum[(tid >> 5) - 1] : 0);
    if (tid < m) part[tid] = excl;
}

__global__ void finalize_scan_kernel(int* __restrict__ off, const int* __restrict__ part,
                                     int* __restrict__ cur, int n, int total) {
    int i = blockIdx.x * blockDim.x + threadIdx.x;
    if (i < n) {
        int o = off[i] + part[blockIdx.x];
        off[i] = o;
        cur[i] = o;
    }
    if (i == 0) off[n] = total;
}

__global__ void permute_kernel(const int* __restrict__ src, const int* __restrict__ dst,
                               const float* __restrict__ val, int* __restrict__ cur,
                               int* __restrict__ src_s, float* __restrict__ val_s, int E) {
    int e = blockIdx.x * blockDim.x + threadIdx.x;
    if (e >= E) return;
    int d = dst[e];
    int pos = atomicAdd(&cur[d], 1);
    src_s[pos] = src[e];
    val_s[pos] = val[e];
}

// ---------------------------------------------------------------------------
// fp16-gather aggregation: out(fp32) = bias + sum_j S16[src]*val (fp32 accum)
// D/8 lanes per node, 16B (8 halves) per lane per edge.
// ---------------------------------------------------------------------------
template <int D>
__global__ void __launch_bounds__(256) agg16_kernel(const __half* __restrict__ S,
                                                    const int* __restrict__ off,
                                                    const int* __restrict__ src_s,
                                                    const float* __restrict__ val_s,
                                                    const float* __restrict__ bias,
                                                    float* __restrict__ out, int N) {
    constexpr int L = D / 8;
    int t = blockIdx.x * blockDim.x + threadIdx.x;
    int node = t / L;
    int lane = t % L;
    if (node >= N) return;

    int beg = __ldg(off + node);
    int end = __ldg(off + node + 1);
    float4 a0 = ((const float4*)bias)[lane * 2];
    float4 a1 = ((const float4*)bias)[lane * 2 + 1];

    int j = beg;
    for (; j + 2 <= end; j += 2) {
        int   s0 = __ldg(src_s + j);
        int   s1 = __ldg(src_s + j + 1);
        float v0 = __ldg(val_s + j);
        float v1 = __ldg(val_s + j + 1);
        uint4 m0 = *(const uint4*)(S + (size_t)s0 * D + lane * 8);
        uint4 m1 = *(const uint4*)(S + (size_t)s1 * D + lane * 8);
        const __half2* h0 = (const __half2*)&m0;
        const __half2* h1 = (const __half2*)&m1;
        float2 f;
        f = __half22float2(h0[0]); a0.x += v0 * f.x; a0.y += v0 * f.y;
        f = __half22float2(h0[1]); a0.z += v0 * f.x; a0.w += v0 * f.y;
        f = __half22float2(h0[2]); a1.x += v0 * f.x; a1.y += v0 * f.y;
        f = __half22float2(h0[3]); a1.z += v0 * f.x; a1.w += v0 * f.y;
        f = __half22float2(h1[0]); a0.x += v1 * f.x; a0.y += v1 * f.y;
        f = __half22float2(h1[1]); a0.z += v1 * f.x; a0.w += v1 * f.y;
        f = __half22float2(h1[2]); a1.x += v1 * f.x; a1.y += v1 * f.y;
        f = __half22float2(h1[3]); a1.z += v1 * f.x; a1.w += v1 * f.y;
    }
    if (j < end) {
        int   s0 = __ldg(src_s + j);
        float v0 = __ldg(val_s + j);
        uint4 m0 = *(const uint4*)(S + (size_t)s0 * D + lane * 8);
        const __half2* h0 = (const __half2*)&m0;
        float2 f;
        f = __half22float2(h0[0]); a0.x += v0 * f.x; a0.y += v0 * f.y;
        f = __half22float2(h0[1]); a0.z += v0 * f.x; a0.w += v0 * f.y;
        f = __half22float2(h0[2]); a1.x += v0 * f.x; a1.y += v0 * f.y;
        f = __half22float2(h0[3]); a1.z += v0 * f.x; a1.w += v0 * f.y;
    }

    float* dst = out + (size_t)node * D + lane * 8;
    *(float4*)dst = a0;
    *(float4*)(dst + 4) = a1;
}

// ---------------------------------------------------------------------------
// Launch (proven topology; fp16 GEMM + fp16 support path everywhere)
// ---------------------------------------------------------------------------
extern "C" void kernel_launch(void* const* d_in, const int* in_sizes, int n_in,
                              void* d_out, int out_size) {
    const float* x    = (const float*)d_in[0];
    const int*   esrc = (const int*)d_in[1];
    const int*   edst = (const int*)d_in[2];
    const float* eval = (const float*)d_in[3];
    const float* W1 = (const float*)d_in[4];
    const float* b1 = (const float*)d_in[5];
    const float* W2 = (const float*)d_in[6];
    const float* b2 = (const float*)d_in[7];
    const float* W3 = (const float*)d_in[8];
    const float* b3 = (const float*)d_in[9];
    const float* W4 = (const float*)d_in[10];
    const float* b4 = (const float*)d_in[11];
    float* out = (float*)d_out;

    float* A = nullptr;
    __half* S16 = nullptr;
    int *off = nullptr, *cur = nullptr, *part = nullptr, *src_s = nullptr;
    float *val_s = nullptr;
    __half *w1, *w2, *w3, *w4;
    cudaGetSymbolAddress((void**)&S16, g_S16);
    cudaGetSymbolAddress((void**)&A, g_A);
    cudaGetSymbolAddress((void**)&off, g_off);
    cudaGetSymbolAddress((void**)&cur, g_cur);
    cudaGetSymbolAddress((void**)&part, g_part);
    cudaGetSymbolAddress((void**)&src_s, g_src_s);
    cudaGetSymbolAddress((void**)&val_s, g_val_s);
    cudaGetSymbolAddress((void**)&w1, g_w16_1);
    cudaGetSymbolAddress((void**)&w2, g_w16_2);
    cudaGetSymbolAddress((void**)&w3, g_w16_3);
    cudaGetSymbolAddress((void**)&w4, g_w16_4);

    // smem sizes: (BM*ASTR + DIN*BSTR) * 2 bytes  (all < 48KB default limit)
    const int SM128 = (128 * 40 + 128 * 136) * 2;  // 45056
    const int SM64  = (128 * 40 + 128 * 72) * 2;   // 28672
    const int SM32  = (128 * 40 + 64 * 40) * 2;    // 15360

    // Persistent side stream + events
    static cudaStream_t s_side = nullptr;
    static cudaEvent_t  ev_fork = nullptr, ev_join = nullptr;
    if (s_side == nullptr) {
        cudaStreamCreateWithFlags(&s_side, cudaStreamNonBlocking);
        cudaEventCreateWithFlags(&ev_fork, cudaEventDisableTiming);
        cudaEventCreateWithFlags(&ev_join, cudaEventDisableTiming);
    }

    const int N = N_NODES;
    const int E = N_EDGES;
    const int tile_grid = (N + 127) / 128;

    // ---- Fork: W2-4 prep + CSR build on side stream ----
    cudaEventRecord(ev_fork, 0);
    cudaStreamWaitEvent(s_side, ev_fork, 0);

    prep_w_kernel<128, 128><<<64, 256, 0, s_side>>>(W2, w2);
    prep_w_kernel<128, 64><<<32, 256, 0, s_side>>>(W3, w3);
    prep_w_kernel<64, 32><<<8, 256, 0, s_side>>>(W4, w4);
    cudaMemsetAsync(cur, 0, N * sizeof(int), s_side);
    hist_kernel<<<(E + 255) / 256, 256, 0, s_side>>>(edst, cur, E);
    scan_block_kernel<<<SCAN_NB, SCAN_B, 0, s_side>>>(cur, off, part, N);
    scan_part_kernel<<<1, SCAN_B, 0, s_side>>>(part, SCAN_NB);
    finalize_scan_kernel<<<SCAN_NB, SCAN_B, 0, s_side>>>(off, part, cur, N, E);
    permute_kernel<<<(E + 255) / 256, 256, 0, s_side>>>(esrc, edst, eval, cur, src_s, val_s, E);
    cudaEventRecord(ev_join, s_side);

    // ---- Layer 1 ----
    prep_w_kernel<128, 128><<<64, 256>>>(W1, w1);
    wgemm_kernel<128, 128, false><<<tile_grid, 256, SM128>>>(x, w1, S16, N);

    cudaStreamWaitEvent(0, ev_join, 0);
    agg16_kernel<128><<<(N * 16 + 255) / 256, 256>>>(S16, off, src_s, val_s, b1, A, N);

    // ---- Layer 2 ----
    wgemm_kernel<128, 128, true><<<tile_grid, 256, SM128>>>(A, w2, S16, N);
    agg16_kernel<128><<<(N * 16 + 255) / 256, 256>>>(S16, off, src_s, val_s, b2, A, N);

    // ---- Layer 3 ----
    wgemm_kernel<128, 64, true><<<tile_grid, 256, SM64>>>(A, w3, S16, N);
    agg16_kernel<64><<<(N * 8 + 255) / 256, 256>>>(S16, off, src_s, val_s, b3, A, N);

    // ---- Layer 4 -> d_out ----
    wgemm_kernel<64, 32, true><<<tile_grid, 256, SM32>>>(A, w4, S16, N);
    agg16_kernel<32><<<(N * 4 + 255) / 256, 256>>>(S16, off, src_s, val_s, b4, out, N);
}